// round 17
// baseline (speedup 1.0000x reference)
#include <cuda_runtime.h>
#include <cuda_bf16.h>
#include <cstdint>
#include <cstdio>

// ---------------------------------------------------------------------------
// GCN_11338713662017: 3-layer GCN + mean pool + log_softmax
//   N=100000 nodes, E=1600000 edges, G=512 graphs, dims 512->128->32->2
// R17: gather128 fused into GEMM2 (no agg1 materialization), double-buffered
// GEMM1, leaner prep (no src/dst staging, dinv fused into scan1).
// ---------------------------------------------------------------------------

#define N_NODES  100000
#define N_EDGES  1600000
#define N_GRAPHS 512
#define F_IN     512
#define H1       128
#define H2       32
#define H3       2
#define SCAN_BLOCKS ((N_NODES + 1023) / 1024)   // 98

// ------------------------- static device scratch ---------------------------
__device__ __nv_bfloat162 g_h1b[(size_t)N_NODES * (H1 / 2)];   // h1 bf16
__device__ __nv_bfloat16  g_h2b[(size_t)N_NODES * H2];         // h2 bf16
__device__ float g_h3[(size_t)N_NODES * H3];
__device__ float g_dinv[N_NODES];
__device__ int   g_deg[N_NODES];
__device__ float g_pool[N_GRAPHS * 2];
__device__ float g_cnt[N_GRAPHS];
__device__ int   g_batch[N_NODES];
__device__ int   g_is64;
// packed bf16-pair weights, n-major: g_w1p[n][p] = {W[2p][n], W[2p+1][n]}
__device__ __align__(16) unsigned int g_w1p[H1 * (F_IN / 2)];
__device__ __align__(16) unsigned int g_w3p[H2 * (H1 / 2)];
// CSR (rebuilt per call; slot order within a node nondeterministic, sum only)
__device__ int   g_off[N_NODES + 1];
__device__ int   g_cursor[N_NODES];
__device__ int   g_csrc[N_EDGES];
__device__ float g_cnorm[N_EDGES];
// scan partials
__device__ int   g_bsum[128];
__device__ int   g_bpre[128];

__device__ __forceinline__ unsigned int f2bf2(float x, float y) {
    __nv_bfloat162 h = __float22bfloat162_rn(make_float2(x, y));
    return *(unsigned int*)&h;
}

// --------------------- zero + index dtype detect (fused) ---------------------
__global__ void k_zero_detect(const void* __restrict__ ei) {
    int i = blockIdx.x * blockDim.x + threadIdx.x;
    if (i < N_NODES) { g_deg[i] = 0; g_cursor[i] = 0; }
    if (i < N_GRAPHS) {
        g_pool[2 * i + 0] = 0.f; g_pool[2 * i + 1] = 0.f; g_cnt[i] = 0.f;
    }
    if (blockIdx.x == 0) {
        // int64 indices are all < N_NODES; int32 data read as u64 packs the
        // next index into the high word -> huge values almost surely.
        __shared__ int ok;
        if (threadIdx.x == 0) ok = 1;
        __syncthreads();
        const unsigned long long* p = (const unsigned long long*)ei;
        for (int j = threadIdx.x; j < 1024; j += blockDim.x)
            if (p[j] >= (unsigned long long)N_NODES) ok = 0;
        __syncthreads();
        if (threadIdx.x == 0) g_is64 = ok;
    }
}

// degree count (dst only) + batch conversion; reads edge_index directly
__global__ void k_deg_batch(const void* __restrict__ ei, const void* __restrict__ bt) {
    int i = blockIdx.x * blockDim.x + threadIdx.x;
    const bool is64 = (g_is64 != 0);
    if (i < N_EDGES) {
        int d = is64 ? (int)((const long long*)ei)[(size_t)N_EDGES + i]
                     : ((const int*)ei)[N_EDGES + i];
        atomicAdd(&g_deg[d], 1);
    }
    if (i < N_NODES)
        g_batch[i] = is64 ? (int)((const long long*)bt)[i] : ((const int*)bt)[i];
}

// ------------------- parallel 3-phase exclusive scan of deg -------------------
// phase 1: per-block exclusive scan into g_off + block sum; dinv fused.
__global__ void k_scan1() {
    __shared__ int wsum[32];
    const int tid = threadIdx.x, lane = tid & 31, w = tid >> 5;
    int i = blockIdx.x * 1024 + tid;
    int v = (i < N_NODES) ? g_deg[i] : 0;
    if (i < N_NODES) g_dinv[i] = rsqrtf((float)v + 1.0f);
    int x = v;
#pragma unroll
    for (int o = 1; o < 32; o <<= 1) {
        int y = __shfl_up_sync(0xffffffffu, x, o);
        if (lane >= o) x += y;
    }
    if (lane == 31) wsum[w] = x;
    __syncthreads();
    if (w == 0) {
        int z = wsum[lane];
#pragma unroll
        for (int o = 1; o < 32; o <<= 1) {
            int y = __shfl_up_sync(0xffffffffu, z, o);
            if (lane >= o) z += y;
        }
        wsum[lane] = z;
    }
    __syncthreads();
    if (i < N_NODES) g_off[i] = (w ? wsum[w - 1] : 0) + x - v;
    if (tid == 0) g_bsum[blockIdx.x] = wsum[31];
}

// phase 2: scan the block sums (1 block, 128 threads)
__global__ void k_scan2() {
    __shared__ int wsum[4];
    const int tid = threadIdx.x, lane = tid & 31, w = tid >> 5;
    int v = (tid < SCAN_BLOCKS) ? g_bsum[tid] : 0;
    int x = v;
#pragma unroll
    for (int o = 1; o < 32; o <<= 1) {
        int y = __shfl_up_sync(0xffffffffu, x, o);
        if (lane >= o) x += y;
    }
    if (lane == 31) wsum[w] = x;
    __syncthreads();
    if (tid == 0) {
        int r = 0;
#pragma unroll
        for (int q = 0; q < 4; q++) { int t = wsum[q]; wsum[q] = r; r += t; }
        g_off[N_NODES] = r;
    }
    __syncthreads();
    if (tid < SCAN_BLOCKS) g_bpre[tid] = wsum[w] + x - v;
}

// phase 3: add block prefixes
__global__ void k_scan3() {
    int i = blockIdx.x * 1024 + threadIdx.x;
    if (i < N_NODES) g_off[i] += g_bpre[blockIdx.x];
}

// ---------------- CSR fill (src + edge norm), reads ei directly ---------------
__global__ void k_fill(const void* __restrict__ ei) {
    int e = blockIdx.x * blockDim.x + threadIdx.x;
    if (e >= N_EDGES) return;
    const bool is64 = (g_is64 != 0);
    int s, d;
    if (is64) {
        s = (int)((const long long*)ei)[e];
        d = (int)((const long long*)ei)[(size_t)N_EDGES + e];
    } else {
        s = ((const int*)ei)[e];
        d = ((const int*)ei)[N_EDGES + e];
    }
    int pos = g_off[d] + atomicAdd(&g_cursor[d], 1);
    g_csrc[pos]  = s;
    g_cnorm[pos] = g_dinv[s] * g_dinv[d];
}

// ------------- W1/W3 -> bf16 pair pack (n-major), one kernel ------------------
__global__ void k_packW(const float* __restrict__ W1, const float* __restrict__ W3) {
    int i = blockIdx.x * blockDim.x + threadIdx.x;
    if (i < H1 * (F_IN / 2)) {                    // W1: 32768
        int p = i >> 7, n = i & 127;
        g_w1p[n * (F_IN / 2) + p] =
            f2bf2(W1[(size_t)(2 * p) * H1 + n], W1[(size_t)(2 * p + 1) * H1 + n]);
    } else {
        int j = i - H1 * (F_IN / 2);              // W3: 2048 = 64p x 32n
        if (j < H2 * (H1 / 2)) {
            int p = j >> 5, n = j & 31;
            g_w3p[n * (H1 / 2) + p] =
                f2bf2(W3[(size_t)(2 * p) * H2 + n], W3[(size_t)(2 * p + 1) * H2 + n]);
        }
    }
}

// ------------------------- bf16 tensor-core GEMM1 ---------------------------
__device__ __forceinline__ void mma_bf16(float* c, const unsigned int* a,
                                         const unsigned int* b) {
    asm volatile(
        "mma.sync.aligned.m16n8k16.row.col.f32.bf16.bf16.f32 "
        "{%0,%1,%2,%3}, {%4,%5,%6,%7}, {%8,%9}, {%0,%1,%2,%3};\n"
        : "+f"(c[0]), "+f"(c[1]), "+f"(c[2]), "+f"(c[3])
        : "r"(a[0]), "r"(a[1]), "r"(a[2]), "r"(a[3]), "r"(b[0]), "r"(b[1]));
}

// C[M,128] = A[M,512] @ W1 -> bf16 g_h1b. 8 warps (4m x 2n), double-buffered.
__global__ __launch_bounds__(256) void k_gemm1_bf16(const float* __restrict__ A,
                                                    int M) {
    __shared__ __align__(16) unsigned int As2[2][128][20];
    __shared__ __align__(16) unsigned int Bs2[2][128][20];
    const int tid  = threadIdx.x;
    const int lane = tid & 31, wid = tid >> 5;
    const int wm = wid & 3, wn = wid >> 2;
    const int g  = lane >> 2, t4 = lane & 3;
    const int row0 = blockIdx.x * 128;

    float acc[2][8][4];
#pragma unroll
    for (int mt = 0; mt < 2; mt++)
#pragma unroll
        for (int nt = 0; nt < 8; nt++)
#pragma unroll
            for (int q = 0; q < 4; q++) acc[mt][nt][q] = 0.f;

    float4 pa[4];
    uint2  pb[4];

    auto loadAB = [&](int k0) {
#pragma unroll
        for (int l = 0; l < 4; l++) {
            int idx = tid + l * 256;
            int r = idx >> 3, c4 = idx & 7;
            int gr = row0 + r;
            pa[l] = (gr < M) ? *(const float4*)(A + (size_t)gr * F_IN + k0 + c4 * 4)
                             : make_float4(0.f, 0.f, 0.f, 0.f);
            pb[l] = *(const uint2*)(g_w1p + r * (F_IN / 2) + (k0 >> 1) + c4 * 2);
        }
    };
    auto storeAB = [&](int buf) {
#pragma unroll
        for (int l = 0; l < 4; l++) {
            int idx = tid + l * 256;
            int r = idx >> 3, c4 = idx & 7;
            As2[buf][r][c4 * 2 + 0] = f2bf2(pa[l].x, pa[l].y);
            As2[buf][r][c4 * 2 + 1] = f2bf2(pa[l].z, pa[l].w);
            *(uint2*)&Bs2[buf][r][c4 * 2] = pb[l];
        }
    };

    loadAB(0);
    storeAB(0);
    __syncthreads();

#pragma unroll 1
    for (int t = 0; t < F_IN / 32; t++) {
        const int buf = t & 1;
        const bool has_next = (t + 1 < F_IN / 32);
        if (has_next) loadAB((t + 1) * 32);

#pragma unroll
        for (int s = 0; s < 2; s++) {
            unsigned int a[2][4], b[8][2];
#pragma unroll
            for (int mt = 0; mt < 2; mt++) {
                int rb = wm * 32 + mt * 16;
                a[mt][0] = As2[buf][rb + g    ][s * 8 + t4    ];
                a[mt][1] = As2[buf][rb + g + 8][s * 8 + t4    ];
                a[mt][2] = As2[buf][rb + g    ][s * 8 + t4 + 4];
                a[mt][3] = As2[buf][rb + g + 8][s * 8 + t4 + 4];
            }
#pragma unroll
            for (int nt = 0; nt < 8; nt++) {
                int col = wn * 64 + nt * 8 + g;
                b[nt][0] = Bs2[buf][col][s * 8 + t4    ];
                b[nt][1] = Bs2[buf][col][s * 8 + t4 + 4];
            }
#pragma unroll
            for (int mt = 0; mt < 2; mt++)
#pragma unroll
                for (int nt = 0; nt < 8; nt++)
                    mma_bf16(acc[mt][nt], a[mt], b[nt]);
        }
        if (has_next) storeAB(buf ^ 1);
        __syncthreads();
    }

#pragma unroll
    for (int mt = 0; mt < 2; mt++) {
        int r = row0 + wm * 32 + mt * 16 + g;
#pragma unroll
        for (int nt = 0; nt < 8; nt++) {
            int cp = (wn * 64 + nt * 8 + 2 * t4) >> 1;
            if (r < M)
                g_h1b[(size_t)r * (H1 / 2) + cp] =
                    __float22bfloat162_rn(make_float2(acc[mt][nt][0], acc[mt][nt][1]));
            if (r + 8 < M)
                g_h1b[(size_t)(r + 8) * (H1 / 2) + cp] =
                    __float22bfloat162_rn(make_float2(acc[mt][nt][2], acc[mt][nt][3]));
        }
    }
}

__device__ __forceinline__ float4 bf4_to_f4(uint2 u) {
    __nv_bfloat162 a = *(__nv_bfloat162*)&u.x;
    __nv_bfloat162 b = *(__nv_bfloat162*)&u.y;
    float2 fa = __bfloat1622float2(a), fb = __bfloat1622float2(b);
    return make_float4(fa.x, fa.y, fb.x, fb.y);
}

// -------------- fused layer 2: gather(A*h1) + relu(+b1) + @W3 ----------------
// Block = 256 thr, 128 dst nodes. Phase 1: warp w gathers nodes w*16..w*16+15
// directly into the GEMM A smem tile (bias+relu fused). Phase 2: bf16 MMA.
__global__ __launch_bounds__(256) void k_fusedL2(const float* __restrict__ bias,
                                                 int M) {
    __shared__ __align__(16) unsigned int As2[128][68];
    __shared__ __align__(16) unsigned int Bs2[32][68];
    const int tid  = threadIdx.x;
    const int lane = tid & 31, wid = tid >> 5;
    const int wm = wid & 3, wn = wid >> 2;
    const int g  = lane >> 2, t4 = lane & 3;
    const int row0 = blockIdx.x * 128;

    // B tile (1024 uint2)
#pragma unroll
    for (int l = 0; l < 4; l++) {
        int idx = tid + l * 256;
        int n = idx >> 5, q2 = idx & 31;
        *(uint2*)&Bs2[n][q2 * 2] = *(const uint2*)(g_w3p + n * (H1 / 2) + q2 * 2);
    }

    // gather phase: 16 nodes per warp
    const float b0 = __ldg(&bias[lane * 4 + 0]);
    const float b1v = __ldg(&bias[lane * 4 + 1]);
    const float b2 = __ldg(&bias[lane * 4 + 2]);
    const float b3v = __ldg(&bias[lane * 4 + 3]);
#pragma unroll 1
    for (int j = 0; j < 16; j++) {
        int r = wid * 16 + j;
        int d = row0 + r;
        if (d >= M) break;
        float di = g_dinv[d];
        float s2 = di * di;
        float4 v = bf4_to_f4(((const uint2*)(g_h1b + (size_t)d * (H1 / 2)))[lane]);
        float4 a0 = make_float4(v.x * s2, v.y * s2, v.z * s2, v.w * s2);
        float4 a1 = make_float4(0.f, 0.f, 0.f, 0.f);
        float4 a2 = make_float4(0.f, 0.f, 0.f, 0.f);
        float4 a3 = make_float4(0.f, 0.f, 0.f, 0.f);
        int e = g_off[d], eend = g_off[d + 1];
        for (; e + 4 <= eend; e += 4) {
            int   s0c = g_csrc[e],     s1c = g_csrc[e + 1];
            int   s2c = g_csrc[e + 2], s3c = g_csrc[e + 3];
            float c0 = g_cnorm[e],     c1 = g_cnorm[e + 1];
            float c2 = g_cnorm[e + 2], c3 = g_cnorm[e + 3];
            float4 v0 = bf4_to_f4(((const uint2*)(g_h1b + (size_t)s0c * (H1 / 2)))[lane]);
            float4 v1 = bf4_to_f4(((const uint2*)(g_h1b + (size_t)s1c * (H1 / 2)))[lane]);
            float4 v2 = bf4_to_f4(((const uint2*)(g_h1b + (size_t)s2c * (H1 / 2)))[lane]);
            float4 v3 = bf4_to_f4(((const uint2*)(g_h1b + (size_t)s3c * (H1 / 2)))[lane]);
            a0.x += v0.x * c0; a0.y += v0.y * c0; a0.z += v0.z * c0; a0.w += v0.w * c0;
            a1.x += v1.x * c1; a1.y += v1.y * c1; a1.z += v1.z * c1; a1.w += v1.w * c1;
            a2.x += v2.x * c2; a2.y += v2.y * c2; a2.z += v2.z * c2; a2.w += v2.w * c2;
            a3.x += v3.x * c3; a3.y += v3.y * c3; a3.z += v3.z * c3; a3.w += v3.w * c3;
        }
        for (; e < eend; e++) {
            int sc = g_csrc[e]; float c = g_cnorm[e];
            float4 v0 = bf4_to_f4(((const uint2*)(g_h1b + (size_t)sc * (H1 / 2)))[lane]);
            a0.x += v0.x * c; a0.y += v0.y * c; a0.z += v0.z * c; a0.w += v0.w * c;
        }
        a0.x += a1.x + a2.x + a3.x; a0.y += a1.y + a2.y + a3.y;
        a0.z += a1.z + a2.z + a3.z; a0.w += a1.w + a2.w + a3.w;
        // bias + relu, pack to bf16 pairs into the GEMM A tile
        As2[r][lane * 2 + 0] = f2bf2(fmaxf(a0.x + b0, 0.f), fmaxf(a0.y + b1v, 0.f));
        As2[r][lane * 2 + 1] = f2bf2(fmaxf(a0.z + b2, 0.f), fmaxf(a0.w + b3v, 0.f));
    }
    __syncthreads();

    // MMA phase: 8 k16 steps (K=128)
    float acc[2][2][4];
#pragma unroll
    for (int mt = 0; mt < 2; mt++)
#pragma unroll
        for (int nt = 0; nt < 2; nt++)
#pragma unroll
            for (int q = 0; q < 4; q++) acc[mt][nt][q] = 0.f;

#pragma unroll
    for (int s = 0; s < 8; s++) {
        unsigned int a[2][4], b[2][2];
#pragma unroll
        for (int mt = 0; mt < 2; mt++) {
            int rb = wm * 32 + mt * 16;
            a[mt][0] = As2[rb + g    ][s * 8 + t4    ];
            a[mt][1] = As2[rb + g + 8][s * 8 + t4    ];
            a[mt][2] = As2[rb + g    ][s * 8 + t4 + 4];
            a[mt][3] = As2[rb + g + 8][s * 8 + t4 + 4];
        }
#pragma unroll
        for (int nt = 0; nt < 2; nt++) {
            int col = wn * 16 + nt * 8 + g;
            b[nt][0] = Bs2[col][s * 8 + t4    ];
            b[nt][1] = Bs2[col][s * 8 + t4 + 4];
        }
#pragma unroll
        for (int mt = 0; mt < 2; mt++)
#pragma unroll
            for (int nt = 0; nt < 2; nt++)
                mma_bf16(acc[mt][nt], a[mt], b[nt]);
    }

#pragma unroll
    for (int mt = 0; mt < 2; mt++) {
        int r = row0 + wm * 32 + mt * 16 + g;
#pragma unroll
        for (int nt = 0; nt < 2; nt++) {
            int cp = wn * 8 + nt * 4 + t4;
            if (r < M)
                ((unsigned int*)(g_h2b + (size_t)r * H2))[cp] =
                    f2bf2(acc[mt][nt][0], acc[mt][nt][1]);
            if (r + 8 < M)
                ((unsigned int*)(g_h2b + (size_t)(r + 8) * H2))[cp] =
                    f2bf2(acc[mt][nt][2], acc[mt][nt][3]);
        }
    }
}

// --------------- gather32 + gemm3 fused: h3 = Â relu(...)@W4 -----------------
__global__ void k_gather32_gemm3(const float* __restrict__ W4,
                                 const float* __restrict__ b3) {
    const int lane = threadIdx.x & 31;
    const int d = (blockIdx.x * blockDim.x + threadIdx.x) >> 5;
    if (d >= N_NODES) return;
    float di = g_dinv[d];
    float acc  = __bfloat162float(g_h2b[(size_t)d * H2 + lane]) * di * di;
    float acc2 = 0.f;
    int e = g_off[d], eend = g_off[d + 1];
    for (; e + 2 <= eend; e += 2) {
        int   s0 = g_csrc[e],  s1 = g_csrc[e + 1];
        float c0 = g_cnorm[e], c1 = g_cnorm[e + 1];
        acc  += __bfloat162float(g_h2b[(size_t)s0 * H2 + lane]) * c0;
        acc2 += __bfloat162float(g_h2b[(size_t)s1 * H2 + lane]) * c1;
    }
    if (e < eend)
        acc += __bfloat162float(g_h2b[(size_t)g_csrc[e] * H2 + lane]) * g_cnorm[e];
    acc += acc2;
    float a  = fmaxf(acc + __ldg(&b3[lane]), 0.f);
    float p0 = a * __ldg(&W4[2 * lane + 0]);
    float p1 = a * __ldg(&W4[2 * lane + 1]);
    const unsigned full = 0xffffffffu;
#pragma unroll
    for (int o = 16; o > 0; o >>= 1) {
        p0 += __shfl_down_sync(full, p0, o);
        p1 += __shfl_down_sync(full, p1, o);
    }
    if (lane == 0) {
        g_h3[2 * d + 0] = p0;
        g_h3[2 * d + 1] = p1;
    }
}

// F=2: one warp per node, lane-parallel over edges; pooling fused.
__global__ void k_gather2_pool() {
    const int lane = threadIdx.x & 31;
    const int d = (blockIdx.x * blockDim.x + threadIdx.x) >> 5;
    if (d >= N_NODES) return;
    float a0 = 0.f, a1 = 0.f;
    int e0 = g_off[d], e1 = g_off[d + 1];
    for (int e = e0 + lane; e < e1; e += 32) {
        int s = g_csrc[e]; float c = g_cnorm[e];
        a0 += g_h3[2 * s + 0] * c;
        a1 += g_h3[2 * s + 1] * c;
    }
    const unsigned full = 0xffffffffu;
#pragma unroll
    for (int o = 16; o > 0; o >>= 1) {
        a0 += __shfl_down_sync(full, a0, o);
        a1 += __shfl_down_sync(full, a1, o);
    }
    if (lane == 0) {
        float di = g_dinv[d], s2 = di * di;
        a0 += g_h3[2 * d + 0] * s2;
        a1 += g_h3[2 * d + 1] * s2;
        int g = g_batch[d];
        atomicAdd(&g_pool[2 * g + 0], a0);
        atomicAdd(&g_pool[2 * g + 1], a1);
        atomicAdd(&g_cnt[g], 1.f);
    }
}

__global__ void k_final(const float* __restrict__ b4, float* __restrict__ out) {
    int g = blockIdx.x * blockDim.x + threadIdx.x;
    if (g >= N_GRAPHS) return;
    float c  = fmaxf(g_cnt[g], 1.f);
    float s0 = g_pool[2 * g + 0] / c + b4[0];
    float s1 = g_pool[2 * g + 1] / c + b4[1];
    float m  = fmaxf(s0, s1);
    float l  = m + logf(expf(s0 - m) + expf(s1 - m));
    out[2 * g + 0] = s0 - l;
    out[2 * g + 1] = s1 - l;
}

// ------------------------------ launcher ------------------------------------
extern "C" void kernel_launch(void* const* d_in, const int* in_sizes, int n_in,
                              void* d_out, int out_size) {
    const float* x  = nullptr;
    const float* W1 = nullptr;
    const float* b1 = nullptr;
    const float* W3 = nullptr;
    const float* b3 = nullptr;
    const float* W4 = nullptr;
    const float* b4 = nullptr;
    const void*  ei = nullptr;
    const void*  bt = nullptr;

    for (int i = 0; i < n_in; i++) {
        switch (in_sizes[i]) {
            case 51200000: x  = (const float*)d_in[i]; break;  // x [100000,512]
            case 65536:    W1 = (const float*)d_in[i]; break;  // [512,128]
            case 128:      b1 = (const float*)d_in[i]; break;
            case 4096:     W3 = (const float*)d_in[i]; break;  // [128,32]
            case 32:       b3 = (const float*)d_in[i]; break;
            case 64:       W4 = (const float*)d_in[i]; break;  // [32,2]
            case 2:        b4 = (const float*)d_in[i]; break;
            case 3200000:  ei = d_in[i]; break;                // edge_index [2,E]
            case 100000:   bt = d_in[i]; break;                // batch [N]
            default: break;                                    // num_graphs scalar
        }
    }

    // Lazily created host-side resources (no device memory).
    static cudaStream_t s_prep = nullptr;
    static cudaEvent_t  ev_fork = nullptr, ev_join = nullptr;
    if (!s_prep) {
        cudaStreamCreateWithFlags(&s_prep, cudaStreamNonBlocking);
        cudaEventCreateWithFlags(&ev_fork, cudaEventDisableTiming);
        cudaEventCreateWithFlags(&ev_join, cudaEventDisableTiming);
    }

    const int T = 256;
    const int WARP_BLOCKS = (N_NODES * 32 + T - 1) / T;   // 1 warp per node

    cudaEventRecord(ev_fork, 0);
    cudaStreamWaitEvent(s_prep, ev_fork, 0);

    // --- prep stream: indices -> CSR with precomputed norms ---
    k_zero_detect<<<(N_NODES + T - 1) / T, T, 0, s_prep>>>(ei);
    k_deg_batch<<<(N_EDGES + T - 1) / T, T, 0, s_prep>>>(ei, bt);
    k_scan1<<<SCAN_BLOCKS, 1024, 0, s_prep>>>();
    k_scan2<<<1, 128, 0, s_prep>>>();
    k_scan3<<<SCAN_BLOCKS, 1024, 0, s_prep>>>();
    k_fill<<<(N_EDGES + T - 1) / T, T, 0, s_prep>>>(ei);
    cudaEventRecord(ev_join, s_prep);

    // --- main stream: pack weights, then bf16 tensor GEMM1 ---
    k_packW<<<(H1 * (F_IN / 2) + H2 * (H1 / 2) + T - 1) / T, T>>>(W1, W3);
    k_gemm1_bf16<<<(N_NODES + 127) / 128, 256>>>(x, N_NODES);

    cudaStreamWaitEvent(0, ev_join, 0);

    // --- fused layer 2: gather + relu(+b1) + GEMM(W3) -> h2 ---
    k_fusedL2<<<(N_NODES + 127) / 128, 256>>>(b1, N_NODES);

    // --- layer 3 fused: gather32 + relu+b3 + W4 -> h3 ---
    k_gather32_gemm3<<<WARP_BLOCKS, T>>>(W4, b3);

    // --- final aggregation + pooling fused ---
    k_gather2_pool<<<WARP_BLOCKS, T>>>();

    // --- log_softmax (b4 folded in) ---
    k_final<<<(N_GRAPHS + T - 1) / T, T>>>(b4, (float*)d_out);
}